// round 1
// baseline (speedup 1.0000x reference)
#include <cuda_runtime.h>
#include <math.h>

// Problem constants
#define Bv 4
#define Lv 1024
#define Cv 768
#define Hv 12
#define Dv 64
#define BH (Bv*Hv)     // 48

// Scratch (device globals: allocation-free per harness rules)
__device__ float g_q[BH*Lv*Dv];                 // [b,h,l,d], pre-scaled by 1/8
__device__ float g_k[BH*Lv*Dv];
__device__ float g_v[BH*Lv*Dv];
__device__ float g_ao[BH*Lv*Dv];                // attention output per head
__device__ float g_s[(size_t)BH*Lv*Lv];         // logits / probs scratch (201MB)

__constant__ float c_wpre[Hv*Hv];
__constant__ float c_wpost[Hv*Hv];

// ---------------------------------------------------------------------------
// K1: projection GEMM. Y[b,h,l,d] = alpha * (X[r,:] @ W[:,c]),  r=(b,l), c=(h,d)
// X: [4096, 768] row-major, W: [768, 768] row-major.
// 64x64 block tile, 16 k-tile, 256 threads, 4x4 microtile.
// ---------------------------------------------------------------------------
__global__ __launch_bounds__(256) void proj_kernel(const float* __restrict__ X,
                                                   const float* __restrict__ W,
                                                   float* __restrict__ Y,
                                                   float alpha) {
    __shared__ float As[16][65];
    __shared__ float Bs[16][64];
    const int tid = threadIdx.x;
    const int tx = tid & 15, ty = tid >> 4;
    const int bx = blockIdx.x, by = blockIdx.y;

    const int arow = tid >> 2;          // 0..63
    const int ak   = (tid & 3) << 2;    // 0,4,8,12
    const int brow = tid >> 4;          // 0..15
    const int bc   = (tid & 15) << 2;   // 0..60

    const float* Aptr = X + (size_t)(by * 64 + arow) * Cv;
    const float* Bptr = W + bx * 64 + bc;

    float acc[4][4] = {};
    for (int k0 = 0; k0 < Cv; k0 += 16) {
        float4 av = *(const float4*)(Aptr + k0 + ak);
        As[ak + 0][arow] = av.x; As[ak + 1][arow] = av.y;
        As[ak + 2][arow] = av.z; As[ak + 3][arow] = av.w;
        *(float4*)&Bs[brow][bc] = *(const float4*)(Bptr + (size_t)(k0 + brow) * Cv);
        __syncthreads();
        #pragma unroll
        for (int kk = 0; kk < 16; kk++) {
            float a[4], b[4];
            #pragma unroll
            for (int i = 0; i < 4; i++) a[i] = As[kk][(ty << 2) + i];
            #pragma unroll
            for (int j = 0; j < 4; j++) b[j] = Bs[kk][(tx << 2) + j];
            #pragma unroll
            for (int i = 0; i < 4; i++)
                #pragma unroll
                for (int j = 0; j < 4; j++)
                    acc[i][j] = fmaf(a[i], b[j], acc[i][j]);
        }
        __syncthreads();
    }
    #pragma unroll
    for (int i = 0; i < 4; i++) {
        int r = by * 64 + (ty << 2) + i;
        int b_ = r >> 10, l = r & 1023;
        #pragma unroll
        for (int j = 0; j < 4; j++) {
            int c = bx * 64 + (tx << 2) + j;
            int h = c >> 6, d = c & 63;
            Y[((size_t)(b_ * Hv + h) * Lv + l) * Dv + d] = acc[i][j] * alpha;
        }
    }
}

// ---------------------------------------------------------------------------
// K2: per-head logits. S[bh, l, k] = sum_d q[bh,l,d] * k[bh,k,d]   (NT GEMM)
// 64x64 tile over (l,k), D=64 fully resident in smem.
// ---------------------------------------------------------------------------
__global__ __launch_bounds__(256) void qk_kernel() {
    __shared__ float Qs[64][65];
    __shared__ float Ks[64][65];
    const int tid = threadIdx.x;
    const int tx = tid & 15, ty = tid >> 4;
    const int bh = blockIdx.z;
    const int l0 = blockIdx.y << 6, k0 = blockIdx.x << 6;

    const float* Q  = g_q + (size_t)bh * Lv * Dv;
    const float* Kp = g_k + (size_t)bh * Lv * Dv;

    const int r  = tid >> 4;          // 0..15
    const int c4 = (tid & 15) << 2;   // 0..60
    #pragma unroll
    for (int i = 0; i < 4; i++) {
        int row = r + (i << 4);
        float4 qv = *(const float4*)(Q + (size_t)(l0 + row) * Dv + c4);
        Qs[row][c4 + 0] = qv.x; Qs[row][c4 + 1] = qv.y;
        Qs[row][c4 + 2] = qv.z; Qs[row][c4 + 3] = qv.w;
        float4 kv = *(const float4*)(Kp + (size_t)(k0 + row) * Dv + c4);
        Ks[row][c4 + 0] = kv.x; Ks[row][c4 + 1] = kv.y;
        Ks[row][c4 + 2] = kv.z; Ks[row][c4 + 3] = kv.w;
    }
    __syncthreads();

    float acc[4][4] = {};
    #pragma unroll 8
    for (int d = 0; d < 64; d++) {
        float a[4], b[4];
        #pragma unroll
        for (int i = 0; i < 4; i++) a[i] = Qs[(ty << 2) + i][d];
        #pragma unroll
        for (int j = 0; j < 4; j++) b[j] = Ks[(tx << 2) + j][d];
        #pragma unroll
        for (int i = 0; i < 4; i++)
            #pragma unroll
            for (int j = 0; j < 4; j++)
                acc[i][j] = fmaf(a[i], b[j], acc[i][j]);
    }
    float* Sp = g_s + (size_t)bh * Lv * Lv;
    #pragma unroll
    for (int i = 0; i < 4; i++)
        #pragma unroll
        for (int j = 0; j < 4; j++)
            Sp[(size_t)(l0 + (ty << 2) + i) * Lv + k0 + (tx << 2) + j] = acc[i][j];
}

// ---------------------------------------------------------------------------
// K3: fused talking-heads: pre-mix -> softmax(k) -> post-mix, one (b,l) per CTA.
// All 12 head-rows (12*1024 f32 = exactly 48KB) in smem; W_pre/W_post in cmem.
// ---------------------------------------------------------------------------
__global__ __launch_bounds__(256) void mix_softmax_kernel() {
    __shared__ float buf[Hv][Lv];   // 49152 bytes
    const int tid = threadIdx.x;
    const int bid = blockIdx.x;
    const int b = bid >> 10, l = bid & 1023;

    // load per-head logits rows
    #pragma unroll
    for (int h = 0; h < Hv; h++) {
        const float* src = g_s + ((size_t)(b * Hv + h) * Lv + l) * Lv;
        for (int k = tid; k < Lv; k += 256) buf[h][k] = src[k];
    }
    __syncthreads();

    // pre-softmax mixing: buf[i][k] = sum_h buf[h][k] * Wpre[h][i]
    // (each thread owns its k columns -> in-place safe without sync)
    for (int k = tid; k < Lv; k += 256) {
        float v[Hv];
        #pragma unroll
        for (int h = 0; h < Hv; h++) v[h] = buf[h][k];
        #pragma unroll
        for (int i = 0; i < Hv; i++) {
            float m = 0.f;
            #pragma unroll
            for (int h = 0; h < Hv; h++) m = fmaf(v[h], c_wpre[h * Hv + i], m);
            buf[i][k] = m;
        }
    }
    __syncthreads();

    // softmax along k: one warp per row (warps cycle over 12 rows)
    const int warp = tid >> 5, lane = tid & 31;
    for (int i = warp; i < Hv; i += 8) {
        float* row = buf[i];
        float mx = -1e30f;
        #pragma unroll
        for (int j = 0; j < 32; j++) mx = fmaxf(mx, row[lane + (j << 5)]);
        #pragma unroll
        for (int o = 16; o > 0; o >>= 1) mx = fmaxf(mx, __shfl_xor_sync(0xffffffffu, mx, o));
        float s = 0.f;
        #pragma unroll
        for (int j = 0; j < 32; j++) {
            float e = __expf(row[lane + (j << 5)] - mx);
            row[lane + (j << 5)] = e;
            s += e;
        }
        #pragma unroll
        for (int o = 16; o > 0; o >>= 1) s += __shfl_xor_sync(0xffffffffu, s, o);
        float inv = 1.f / s;
        #pragma unroll
        for (int j = 0; j < 32; j++) row[lane + (j << 5)] *= inv;
    }
    __syncthreads();

    // post-softmax mixing + writeback: P[i][k] = sum_h buf[h][k] * Wpost[h][i]
    for (int k = tid; k < Lv; k += 256) {
        float v[Hv];
        #pragma unroll
        for (int h = 0; h < Hv; h++) v[h] = buf[h][k];
        #pragma unroll
        for (int i = 0; i < Hv; i++) {
            float m = 0.f;
            #pragma unroll
            for (int h = 0; h < Hv; h++) m = fmaf(v[h], c_wpost[h * Hv + i], m);
            g_s[((size_t)(b * Hv + i) * Lv + l) * Lv + k] = m;
        }
    }
}

// ---------------------------------------------------------------------------
// K4: P @ V per (b,h):  ao[bh,l,d] = sum_k P[bh,l,k] * v[bh,k,d]
// 64(l) x 64(d) tile (d fully covered), k-tiles of 32.
// ---------------------------------------------------------------------------
__global__ __launch_bounds__(256) void pv_kernel() {
    __shared__ float Ps[64][33];
    __shared__ float Vs[32][64];
    const int tid = threadIdx.x;
    const int tx = tid & 15, ty = tid >> 4;
    const int bh = blockIdx.y;
    const int l0 = blockIdx.x << 6;

    const float* P = g_s + (size_t)bh * Lv * Lv;
    const float* V = g_v + (size_t)bh * Lv * Dv;

    const int prow = tid >> 3;          // 0..31
    const int pc   = (tid & 7) << 2;    // 0..28
    const int vrow = tid >> 4;          // 0..15
    const int vc   = (tid & 15) << 2;   // 0..60

    float acc[4][4] = {};
    for (int kt = 0; kt < Lv; kt += 32) {
        #pragma unroll
        for (int i = 0; i < 2; i++) {
            int row = prow + (i << 5);
            float4 pv = *(const float4*)(P + (size_t)(l0 + row) * Lv + kt + pc);
            Ps[row][pc + 0] = pv.x; Ps[row][pc + 1] = pv.y;
            Ps[row][pc + 2] = pv.z; Ps[row][pc + 3] = pv.w;
        }
        #pragma unroll
        for (int i = 0; i < 2; i++) {
            int row = vrow + (i << 4);
            *(float4*)&Vs[row][vc] = *(const float4*)(V + (size_t)(kt + row) * Dv + vc);
        }
        __syncthreads();
        #pragma unroll 8
        for (int kk = 0; kk < 32; kk++) {
            float a[4], b[4];
            #pragma unroll
            for (int i = 0; i < 4; i++) a[i] = Ps[(ty << 2) + i][kk];
            #pragma unroll
            for (int j = 0; j < 4; j++) b[j] = Vs[kk][(tx << 2) + j];
            #pragma unroll
            for (int i = 0; i < 4; i++)
                #pragma unroll
                for (int j = 0; j < 4; j++)
                    acc[i][j] = fmaf(a[i], b[j], acc[i][j]);
        }
        __syncthreads();
    }
    #pragma unroll
    for (int i = 0; i < 4; i++)
        #pragma unroll
        for (int j = 0; j < 4; j++)
            g_ao[((size_t)bh * Lv + l0 + (ty << 2) + i) * Dv + (tx << 2) + j] = acc[i][j];
}

// ---------------------------------------------------------------------------
// K5: output GEMM. out[r,c] = sum_j AO[r,j] * Wout[j,c],
// AO read from [b,h,l,d] layout (r=(b,l), j=(h,d)). out: [4096,768] row-major.
// ---------------------------------------------------------------------------
__global__ __launch_bounds__(256) void out_kernel(const float* __restrict__ W,
                                                  float* __restrict__ O) {
    __shared__ float As[16][65];
    __shared__ float Bs[16][64];
    const int tid = threadIdx.x;
    const int tx = tid & 15, ty = tid >> 4;
    const int bx = blockIdx.x, by = blockIdx.y;

    const int arow = tid >> 2;
    const int ak   = (tid & 3) << 2;
    const int r    = by * 64 + arow;
    const int b_   = r >> 10, l = r & 1023;
    const int brow = tid >> 4;
    const int bc   = (tid & 15) << 2;

    float acc[4][4] = {};
    for (int k0 = 0; k0 < Cv; k0 += 16) {
        int kap = k0 + ak;
        int h = kap >> 6, d = kap & 63;
        float4 av = *(const float4*)(g_ao + ((size_t)(b_ * Hv + h) * Lv + l) * Dv + d);
        As[ak + 0][arow] = av.x; As[ak + 1][arow] = av.y;
        As[ak + 2][arow] = av.z; As[ak + 3][arow] = av.w;
        *(float4*)&Bs[brow][bc] =
            *(const float4*)(W + (size_t)(k0 + brow) * Cv + bx * 64 + bc);
        __syncthreads();
        #pragma unroll
        for (int kk = 0; kk < 16; kk++) {
            float a[4], b[4];
            #pragma unroll
            for (int i = 0; i < 4; i++) a[i] = As[kk][(ty << 2) + i];
            #pragma unroll
            for (int j = 0; j < 4; j++) b[j] = Bs[kk][(tx << 2) + j];
            #pragma unroll
            for (int i = 0; i < 4; i++)
                #pragma unroll
                for (int j = 0; j < 4; j++)
                    acc[i][j] = fmaf(a[i], b[j], acc[i][j]);
        }
        __syncthreads();
    }
    #pragma unroll
    for (int i = 0; i < 4; i++) {
        int rr = by * 64 + (ty << 2) + i;
        #pragma unroll
        for (int j = 0; j < 4; j++)
            O[(size_t)rr * Cv + bx * 64 + (tx << 2) + j] = acc[i][j];
    }
}

// ---------------------------------------------------------------------------
extern "C" void kernel_launch(void* const* d_in, const int* in_sizes, int n_in,
                              void* d_out, int out_size) {
    const float* xq   = (const float*)d_in[0];
    const float* xkv  = (const float*)d_in[1];
    const float* Wq   = (const float*)d_in[2];
    const float* Wk   = (const float*)d_in[3];
    const float* Wv   = (const float*)d_in[4];
    const float* Wout = (const float*)d_in[5];

    // talking-heads matrices -> constant memory (capturable D2D copy)
    cudaMemcpyToSymbolAsync(c_wpre,  d_in[6], Hv * Hv * sizeof(float), 0,
                            cudaMemcpyDeviceToDevice, 0);
    cudaMemcpyToSymbolAsync(c_wpost, d_in[7], Hv * Hv * sizeof(float), 0,
                            cudaMemcpyDeviceToDevice, 0);

    float *qp, *kp, *vp;
    cudaGetSymbolAddress((void**)&qp, g_q);
    cudaGetSymbolAddress((void**)&kp, g_k);
    cudaGetSymbolAddress((void**)&vp, g_v);

    dim3 blk(256);
    // Q scaled by 1/sqrt(D) = 1/8
    proj_kernel<<<dim3(12, 64), blk>>>(xq,  Wq, qp, 0.125f);
    proj_kernel<<<dim3(12, 64), blk>>>(xkv, Wk, kp, 1.0f);
    proj_kernel<<<dim3(12, 64), blk>>>(xkv, Wv, vp, 1.0f);

    qk_kernel<<<dim3(16, 16, 48), blk>>>();
    mix_softmax_kernel<<<dim3(Bv * Lv), blk>>>();
    pv_kernel<<<dim3(16, 48), blk>>>();
    out_kernel<<<dim3(12, 64), blk>>>(Wout, (float*)d_out);
}